// round 13
// baseline (speedup 1.0000x reference)
#include <cuda_runtime.h>

// SpatialTransformer: out = trilinear_sample(src, identity_grid + flow), border clamp.
// src:  [1,1,160,192,160] f32   d_in[0]
// flow: [1,3,160,192,160] f32   d_in[1]  (channel-planar: d,h,w displacement)
// grid: identity meshgrid       d_in[2]  (IGNORED - recomputed from indices)
// out:  [1,1,160,192,160] f32
//
// Math collapse (verified, rel_err 2.6e-5):
//   ux = (w + flow[2]) * W/(W-1) - 0.5 ; clamp [0, W-1]; trilinear w/ clamped +1.
//
// Settled by R6..R12 evidence:
//  - 3D tile 32x8x4 per block -> gathers L1-resident (R11: L2% 68->43). KEEP.
//  - aligned float2 pair + 25% predicated fix-up = best gather encoding. KEEP.
//  - shadow-copy and other footprint-doubling tricks REGRESS (R10/R12).
//  - front-batched flow loads (one latency exposure). KEEP.
// R13: same structure, higher warp count for latency hiding: store results
// in-loop (kills res[] regs) + __launch_bounds__(256,7) -> 7 blocks/SM.

#define DD 160
#define HH 192
#define WW 160
#define PLANE (HH * WW)
#define NN (DD * HH * WW)
#define ZB 4   // z-batch per thread

__global__ __launch_bounds__(256, 7) void st_warp_tile7_kernel(
    const float* __restrict__ src,
    const float* __restrict__ flow,
    float* __restrict__ out)
{
    // 3D tile: 32 (x) x 8 (h) x ZB (z) voxels per block, 256 threads
    const int w  = blockIdx.x * 32 + threadIdx.x;
    const int h  = blockIdx.y * 8 + threadIdx.y;
    const int d0 = blockIdx.z * ZB;
    const int base = (d0 * HH + h) * WW + w;

    const float sx = (float)WW / (float)(WW - 1);
    const float sy = (float)HH / (float)(HH - 1);
    const float sz = (float)DD / (float)(DD - 1);

    // front-batched flow loads (one latency exposure; warp-coalesced: tx fastest)
    float fdv[ZB], fhv[ZB], fwv[ZB];
#pragma unroll
    for (int k = 0; k < ZB; k++) {
        const int idx = base + k * PLANE;
        fdv[k] = __ldg(flow + idx);            // D-displacement
        fhv[k] = __ldg(flow + NN + idx);       // H-displacement
        fwv[k] = __ldg(flow + 2 * NN + idx);   // W-displacement
    }

#pragma unroll
    for (int k = 0; k < ZB; k++) {
        const int d = d0 + k;

        float ux = ((float)w + fwv[k]) * sx - 0.5f;
        float uy = ((float)h + fhv[k]) * sy - 0.5f;
        float uz = ((float)d + fdv[k]) * sz - 0.5f;

        ux = fminf(fmaxf(ux, 0.0f), (float)(WW - 1));
        uy = fminf(fmaxf(uy, 0.0f), (float)(HH - 1));
        uz = fminf(fmaxf(uz, 0.0f), (float)(DD - 1));

        // coords >= 0 -> truncation == floor
        const int x0 = (int)ux;
        const int y0 = (int)uy;
        const int z0 = (int)uz;
        const float ax = ux - (float)x0;
        const float ay = uy - (float)y0;
        const float az = uz - (float)z0;

        const int x1 = min(x0 + 1, WW - 1);
        const int y1 = min(y0 + 1, HH - 1);
        const int z1 = min(z0 + 1, DD - 1);

        const int x0a = x0 & ~1;            // 8B-aligned pair start
        const bool odd = (x0 & 1) != 0;

        const int zy00 = (z0 * HH + y0) * WW;
        const int zy01 = (z0 * HH + y1) * WW;
        const int zy10 = (z1 * HH + y0) * WW;
        const int zy11 = (z1 * HH + y1) * WW;

        const float2 v00 = __ldg((const float2*)(src + zy00 + x0a));
        const float2 v01 = __ldg((const float2*)(src + zy01 + x0a));
        const float2 v10 = __ldg((const float2*)(src + zy10 + x0a));
        const float2 v11 = __ldg((const float2*)(src + zy11 + x0a));

        // predicated fix-up loads for odd x0 (pair straddles float2 boundary)
        float e00 = v00.y, e01 = v01.y, e10 = v10.y, e11 = v11.y;
        if (odd) e00 = __ldg(src + zy00 + x1);
        if (odd) e01 = __ldg(src + zy01 + x1);
        if (odd) e10 = __ldg(src + zy10 + x1);
        if (odd) e11 = __ldg(src + zy11 + x1);

        const float l00 = odd ? v00.y : v00.x;
        const float l01 = odd ? v01.y : v01.x;
        const float l10 = odd ? v10.y : v10.x;
        const float l11 = odd ? v11.y : v11.x;

        const float c00 = fmaf(ax, e00 - l00, l00);
        const float c01 = fmaf(ax, e01 - l01, l01);
        const float c10 = fmaf(ax, e10 - l10, l10);
        const float c11 = fmaf(ax, e11 - l11, l11);

        const float c0 = fmaf(ay, c01 - c00, c00);
        const float c1 = fmaf(ay, c11 - c10, c10);
        // store in-loop: no res[] array -> lower register footprint
        out[base + k * PLANE] = fmaf(az, c1 - c0, c0);
    }
}

extern "C" void kernel_launch(void* const* d_in, const int* in_sizes, int n_in,
                              void* d_out, int out_size)
{
    const float* src  = (const float*)d_in[0];
    const float* flow = (const float*)d_in[1];
    // d_in[2] (identity grid) intentionally unused — recomputed from indices.
    float* out = (float*)d_out;

    dim3 block(32, 8, 1);
    dim3 grid(WW / 32, HH / 8, DD / ZB);   // 5 x 24 x 40 = 4800 blocks
    st_warp_tile7_kernel<<<grid, block>>>(src, flow, out);
}

// round 14
// speedup vs baseline: 1.1642x; 1.1642x over previous
#include <cuda_runtime.h>

// SpatialTransformer: out = trilinear_sample(src, identity_grid + flow), border clamp.
// src:  [1,1,160,192,160] f32   d_in[0]
// flow: [1,3,160,192,160] f32   d_in[1]  (channel-planar: d,h,w displacement)
// grid: identity meshgrid       d_in[2]  (IGNORED - recomputed from indices)
// out:  [1,1,160,192,160] f32
//
// Math collapse (verified, rel_err 2.6e-5):
//   ux = (w + flow[2]) * W/(W-1) - 0.5 ; clamp [0, W-1]; trilinear w/ clamped +1.
//
// Settled model (R6..R13): perf = L1-resident gather reuse.
//  - 3D tiling keeps gathers in L1 (R11 champion, 51.7us).
//  - raising occupancy REGRESSES (R8/R9/R13): more blocks/SM -> aggregate
//    tile footprints thrash 228KB L1.
//  - footprint-doubling tricks REGRESS (R10/R12).
// R14: bigger-and-fewer blocks. 512 threads, tile 32x16x4: per-SM aggregate
// footprint 3x268KB ~ 800KB (vs 6x207KB=1.24MB), per-tile reuse +56%.
// Everything else identical to R11.

#define DD 160
#define HH 192
#define WW 160
#define PLANE (HH * WW)
#define NN (DD * HH * WW)
#define ZB 4   // z-batch per thread

__global__ void st_warp_tile512_kernel(
    const float* __restrict__ src,
    const float* __restrict__ flow,
    float* __restrict__ out)
{
    // 3D tile: 32 (x) x 16 (h) x ZB (z) voxels per block, 512 threads
    const int w  = blockIdx.x * 32 + threadIdx.x;
    const int h  = blockIdx.y * 16 + threadIdx.y;
    const int d0 = blockIdx.z * ZB;
    const int base = (d0 * HH + h) * WW + w;

    const float sx = (float)WW / (float)(WW - 1);
    const float sy = (float)HH / (float)(HH - 1);
    const float sz = (float)DD / (float)(DD - 1);

    // front-batched flow loads (one latency exposure; warp-coalesced: tx fastest)
    float fdv[ZB], fhv[ZB], fwv[ZB];
#pragma unroll
    for (int k = 0; k < ZB; k++) {
        const int idx = base + k * PLANE;
        fdv[k] = __ldg(flow + idx);            // D-displacement
        fhv[k] = __ldg(flow + NN + idx);       // H-displacement
        fwv[k] = __ldg(flow + 2 * NN + idx);   // W-displacement
    }

    float res[ZB];
#pragma unroll
    for (int k = 0; k < ZB; k++) {
        const int d = d0 + k;

        float ux = ((float)w + fwv[k]) * sx - 0.5f;
        float uy = ((float)h + fhv[k]) * sy - 0.5f;
        float uz = ((float)d + fdv[k]) * sz - 0.5f;

        ux = fminf(fmaxf(ux, 0.0f), (float)(WW - 1));
        uy = fminf(fmaxf(uy, 0.0f), (float)(HH - 1));
        uz = fminf(fmaxf(uz, 0.0f), (float)(DD - 1));

        // coords >= 0 -> truncation == floor
        const int x0 = (int)ux;
        const int y0 = (int)uy;
        const int z0 = (int)uz;
        const float ax = ux - (float)x0;
        const float ay = uy - (float)y0;
        const float az = uz - (float)z0;

        const int x1 = min(x0 + 1, WW - 1);
        const int y1 = min(y0 + 1, HH - 1);
        const int z1 = min(z0 + 1, DD - 1);

        const int x0a = x0 & ~1;            // 8B-aligned pair start
        const bool odd = (x0 & 1) != 0;

        const int zy00 = (z0 * HH + y0) * WW;
        const int zy01 = (z0 * HH + y1) * WW;
        const int zy10 = (z1 * HH + y0) * WW;
        const int zy11 = (z1 * HH + y1) * WW;

        const float2 v00 = __ldg((const float2*)(src + zy00 + x0a));
        const float2 v01 = __ldg((const float2*)(src + zy01 + x0a));
        const float2 v10 = __ldg((const float2*)(src + zy10 + x0a));
        const float2 v11 = __ldg((const float2*)(src + zy11 + x0a));

        // predicated fix-up loads for odd x0 (pair straddles float2 boundary)
        float e00 = v00.y, e01 = v01.y, e10 = v10.y, e11 = v11.y;
        if (odd) e00 = __ldg(src + zy00 + x1);
        if (odd) e01 = __ldg(src + zy01 + x1);
        if (odd) e10 = __ldg(src + zy10 + x1);
        if (odd) e11 = __ldg(src + zy11 + x1);

        const float l00 = odd ? v00.y : v00.x;
        const float l01 = odd ? v01.y : v01.x;
        const float l10 = odd ? v10.y : v10.x;
        const float l11 = odd ? v11.y : v11.x;

        const float c00 = fmaf(ax, e00 - l00, l00);
        const float c01 = fmaf(ax, e01 - l01, l01);
        const float c10 = fmaf(ax, e10 - l10, l10);
        const float c11 = fmaf(ax, e11 - l11, l11);

        const float c0 = fmaf(ay, c01 - c00, c00);
        const float c1 = fmaf(ay, c11 - c10, c10);
        res[k] = fmaf(az, c1 - c0, c0);
    }

#pragma unroll
    for (int k = 0; k < ZB; k++)
        out[base + k * PLANE] = res[k];
}

extern "C" void kernel_launch(void* const* d_in, const int* in_sizes, int n_in,
                              void* d_out, int out_size)
{
    const float* src  = (const float*)d_in[0];
    const float* flow = (const float*)d_in[1];
    // d_in[2] (identity grid) intentionally unused — recomputed from indices.
    float* out = (float*)d_out;

    dim3 block(32, 16, 1);
    dim3 grid(WW / 32, HH / 16, DD / ZB);   // 5 x 12 x 40 = 2400 blocks
    st_warp_tile512_kernel<<<grid, block>>>(src, flow, out);
}

// round 15
// speedup vs baseline: 1.1702x; 1.0052x over previous
#include <cuda_runtime.h>

// SpatialTransformer: out = trilinear_sample(src, identity_grid + flow), border clamp.
// src:  [1,1,160,192,160] f32   d_in[0]
// flow: [1,3,160,192,160] f32   d_in[1]  (channel-planar: d,h,w displacement)
// grid: identity meshgrid       d_in[2]  (IGNORED - recomputed from indices)
// out:  [1,1,160,192,160] f32
//
// Math collapse (verified, rel_err 2.6e-5):
//   ux = (w + flow[2]) * W/(W-1) - 0.5 ; clamp [0, W-1]; trilinear w/ clamped +1.
//
// Settled model (R6..R14): perf = L1-resident gather reuse + per-thread MLP.
//  - 3D tiling keeps gathers in L1 (R11/R14 wins: L2% 68->43->34).
//  - raising occupancy REGRESSES (R8/R9/R13): aggregate footprints thrash L1.
//  - footprint doubling REGRESSES (R10/R12).
//  - nothing saturated at R14 (L1 74, issue 35, occ 67) => latency-bound.
// R15: deepen per-thread gather chains: ZB=8, tile 32x8x8 (256 thr, same
// 2048-voxel block volume, same effective row footprint). Front-batched flow
// (one exposure, R7-proven), in-loop output stores to cap registers.

#define DD 160
#define HH 192
#define WW 160
#define PLANE (HH * WW)
#define NN (DD * HH * WW)
#define ZB 8   // z-batch per thread

__global__ void st_warp_tile_z8_kernel(
    const float* __restrict__ src,
    const float* __restrict__ flow,
    float* __restrict__ out)
{
    // 3D tile: 32 (x) x 8 (h) x ZB (z) voxels per block, 256 threads
    const int w  = blockIdx.x * 32 + threadIdx.x;
    const int h  = blockIdx.y * 8 + threadIdx.y;
    const int d0 = blockIdx.z * ZB;
    const int base = (d0 * HH + h) * WW + w;

    const float sx = (float)WW / (float)(WW - 1);
    const float sy = (float)HH / (float)(HH - 1);
    const float sz = (float)DD / (float)(DD - 1);

    // front-batched flow loads (one latency exposure; warp-coalesced: tx fastest)
    float fdv[ZB], fhv[ZB], fwv[ZB];
#pragma unroll
    for (int k = 0; k < ZB; k++) {
        const int idx = base + k * PLANE;
        fdv[k] = __ldg(flow + idx);            // D-displacement
        fhv[k] = __ldg(flow + NN + idx);       // H-displacement
        fwv[k] = __ldg(flow + 2 * NN + idx);   // W-displacement
    }

#pragma unroll
    for (int k = 0; k < ZB; k++) {
        const int d = d0 + k;

        float ux = ((float)w + fwv[k]) * sx - 0.5f;
        float uy = ((float)h + fhv[k]) * sy - 0.5f;
        float uz = ((float)d + fdv[k]) * sz - 0.5f;

        ux = fminf(fmaxf(ux, 0.0f), (float)(WW - 1));
        uy = fminf(fmaxf(uy, 0.0f), (float)(HH - 1));
        uz = fminf(fmaxf(uz, 0.0f), (float)(DD - 1));

        // coords >= 0 -> truncation == floor
        const int x0 = (int)ux;
        const int y0 = (int)uy;
        const int z0 = (int)uz;
        const float ax = ux - (float)x0;
        const float ay = uy - (float)y0;
        const float az = uz - (float)z0;

        const int x1 = min(x0 + 1, WW - 1);
        const int y1 = min(y0 + 1, HH - 1);
        const int z1 = min(z0 + 1, DD - 1);

        const int x0a = x0 & ~1;            // 8B-aligned pair start
        const bool odd = (x0 & 1) != 0;

        const int zy00 = (z0 * HH + y0) * WW;
        const int zy01 = (z0 * HH + y1) * WW;
        const int zy10 = (z1 * HH + y0) * WW;
        const int zy11 = (z1 * HH + y1) * WW;

        const float2 v00 = __ldg((const float2*)(src + zy00 + x0a));
        const float2 v01 = __ldg((const float2*)(src + zy01 + x0a));
        const float2 v10 = __ldg((const float2*)(src + zy10 + x0a));
        const float2 v11 = __ldg((const float2*)(src + zy11 + x0a));

        // predicated fix-up loads for odd x0 (pair straddles float2 boundary)
        float e00 = v00.y, e01 = v01.y, e10 = v10.y, e11 = v11.y;
        if (odd) e00 = __ldg(src + zy00 + x1);
        if (odd) e01 = __ldg(src + zy01 + x1);
        if (odd) e10 = __ldg(src + zy10 + x1);
        if (odd) e11 = __ldg(src + zy11 + x1);

        const float l00 = odd ? v00.y : v00.x;
        const float l01 = odd ? v01.y : v01.x;
        const float l10 = odd ? v10.y : v10.x;
        const float l11 = odd ? v11.y : v11.x;

        const float c00 = fmaf(ax, e00 - l00, l00);
        const float c01 = fmaf(ax, e01 - l01, l01);
        const float c10 = fmaf(ax, e10 - l10, l10);
        const float c11 = fmaf(ax, e11 - l11, l11);

        const float c0 = fmaf(ay, c01 - c00, c00);
        const float c1 = fmaf(ay, c11 - c10, c10);
        // in-loop store: keeps live registers bounded at ZB=8
        out[base + k * PLANE] = fmaf(az, c1 - c0, c0);
    }
}

extern "C" void kernel_launch(void* const* d_in, const int* in_sizes, int n_in,
                              void* d_out, int out_size)
{
    const float* src  = (const float*)d_in[0];
    const float* flow = (const float*)d_in[1];
    // d_in[2] (identity grid) intentionally unused — recomputed from indices.
    float* out = (float*)d_out;

    dim3 block(32, 8, 1);
    dim3 grid(WW / 32, HH / 8, DD / ZB);   // 5 x 24 x 20 = 2400 blocks
    st_warp_tile_z8_kernel<<<grid, block>>>(src, flow, out);
}

// round 16
// speedup vs baseline: 1.2206x; 1.0430x over previous
#include <cuda_runtime.h>

// SpatialTransformer: out = trilinear_sample(src, identity_grid + flow), border clamp.
// src:  [1,1,160,192,160] f32   d_in[0]
// flow: [1,3,160,192,160] f32   d_in[1]  (channel-planar: d,h,w displacement)
// grid: identity meshgrid       d_in[2]  (IGNORED - recomputed from indices)
// out:  [1,1,160,192,160] f32
//
// Math collapse (verified, rel_err 2.6e-5):
//   ux = (w + flow[2]) * W/(W-1) - 0.5 ; clamp [0, W-1]; trilinear w/ clamped +1.
//
// Settled model (R6..R15): latency-bound at an MLP ceiling set by the
// regfile/L1-capacity trade. 3D tiling = L1-resident gathers (R11/R14);
// occupancy pushes thrash L1 (R8/R9/R13); footprint doubling regresses
// (R10/R12); ZB=8 chains ~= ZB=4 x 2 blocks (R14~R15 within noise).
// R16: stop streaming zero-reuse data through L1. flow reads -> __ldcs
// (evict-first), out stores -> __stcs. Keeps 228KB L1 dedicated to src
// gather tiles -> higher hit rate -> less exposed latency. Structure
// otherwise identical to R15 (best).

#define DD 160
#define HH 192
#define WW 160
#define PLANE (HH * WW)
#define NN (DD * HH * WW)
#define ZB 8   // z-batch per thread

__global__ void st_warp_tile_cs_kernel(
    const float* __restrict__ src,
    const float* __restrict__ flow,
    float* __restrict__ out)
{
    // 3D tile: 32 (x) x 8 (h) x ZB (z) voxels per block, 256 threads
    const int w  = blockIdx.x * 32 + threadIdx.x;
    const int h  = blockIdx.y * 8 + threadIdx.y;
    const int d0 = blockIdx.z * ZB;
    const int base = (d0 * HH + h) * WW + w;

    const float sx = (float)WW / (float)(WW - 1);
    const float sy = (float)HH / (float)(HH - 1);
    const float sz = (float)DD / (float)(DD - 1);

    // front-batched flow loads, streaming (evict-first: zero reuse, keep L1 for src)
    float fdv[ZB], fhv[ZB], fwv[ZB];
#pragma unroll
    for (int k = 0; k < ZB; k++) {
        const int idx = base + k * PLANE;
        fdv[k] = __ldcs(flow + idx);            // D-displacement
        fhv[k] = __ldcs(flow + NN + idx);       // H-displacement
        fwv[k] = __ldcs(flow + 2 * NN + idx);   // W-displacement
    }

#pragma unroll
    for (int k = 0; k < ZB; k++) {
        const int d = d0 + k;

        float ux = ((float)w + fwv[k]) * sx - 0.5f;
        float uy = ((float)h + fhv[k]) * sy - 0.5f;
        float uz = ((float)d + fdv[k]) * sz - 0.5f;

        ux = fminf(fmaxf(ux, 0.0f), (float)(WW - 1));
        uy = fminf(fmaxf(uy, 0.0f), (float)(HH - 1));
        uz = fminf(fmaxf(uz, 0.0f), (float)(DD - 1));

        // coords >= 0 -> truncation == floor
        const int x0 = (int)ux;
        const int y0 = (int)uy;
        const int z0 = (int)uz;
        const float ax = ux - (float)x0;
        const float ay = uy - (float)y0;
        const float az = uz - (float)z0;

        const int x1 = min(x0 + 1, WW - 1);
        const int y1 = min(y0 + 1, HH - 1);
        const int z1 = min(z0 + 1, DD - 1);

        const int x0a = x0 & ~1;            // 8B-aligned pair start
        const bool odd = (x0 & 1) != 0;

        const int zy00 = (z0 * HH + y0) * WW;
        const int zy01 = (z0 * HH + y1) * WW;
        const int zy10 = (z1 * HH + y0) * WW;
        const int zy11 = (z1 * HH + y1) * WW;

        const float2 v00 = __ldg((const float2*)(src + zy00 + x0a));
        const float2 v01 = __ldg((const float2*)(src + zy01 + x0a));
        const float2 v10 = __ldg((const float2*)(src + zy10 + x0a));
        const float2 v11 = __ldg((const float2*)(src + zy11 + x0a));

        // predicated fix-up loads for odd x0 (pair straddles float2 boundary)
        float e00 = v00.y, e01 = v01.y, e10 = v10.y, e11 = v11.y;
        if (odd) e00 = __ldg(src + zy00 + x1);
        if (odd) e01 = __ldg(src + zy01 + x1);
        if (odd) e10 = __ldg(src + zy10 + x1);
        if (odd) e11 = __ldg(src + zy11 + x1);

        const float l00 = odd ? v00.y : v00.x;
        const float l01 = odd ? v01.y : v01.x;
        const float l10 = odd ? v10.y : v10.x;
        const float l11 = odd ? v11.y : v11.x;

        const float c00 = fmaf(ax, e00 - l00, l00);
        const float c01 = fmaf(ax, e01 - l01, l01);
        const float c10 = fmaf(ax, e10 - l10, l10);
        const float c11 = fmaf(ax, e11 - l11, l11);

        const float c0 = fmaf(ay, c01 - c00, c00);
        const float c1 = fmaf(ay, c11 - c10, c10);
        // streaming store: no L1 allocation for write-once output
        __stcs(out + base + k * PLANE, fmaf(az, c1 - c0, c0));
    }
}

extern "C" void kernel_launch(void* const* d_in, const int* in_sizes, int n_in,
                              void* d_out, int out_size)
{
    const float* src  = (const float*)d_in[0];
    const float* flow = (const float*)d_in[1];
    // d_in[2] (identity grid) intentionally unused — recomputed from indices.
    float* out = (float*)d_out;

    dim3 block(32, 8, 1);
    dim3 grid(WW / 32, HH / 8, DD / ZB);   // 5 x 24 x 20 = 2400 blocks
    st_warp_tile_cs_kernel<<<grid, block>>>(src, flow, out);
}